// round 13
// baseline (speedup 1.0000x reference)
#include <cuda_runtime.h>

// ---------------------------------------------------------------------------
// CarryII R13: R12 + PROPER zero/scatter interleave.
// R12 appended zero work as tail blocks -> scheduled after scatter blocks,
// so the write-only zero traffic barely overlapped the read-heavy scatter.
// R13: every scatter thread also zeroes a strided share of the NEXT block
// (grid-strided within the same kernel), so zero writes pipeline with
// gather reads + REDs across the whole kernel duration.
// Scatter path unchanged (8 lanes/edge, 2 edges/thread, red.v4, __ldcs idx).
// ---------------------------------------------------------------------------

static constexpr int FEAT_D = 32;

__global__ void zero_f4_kernel(float4* __restrict__ out, long long n4) {
    long long i = blockIdx.x * (long long)blockDim.x + threadIdx.x;
    if (i < n4) out[i] = make_float4(0.f, 0.f, 0.f, 0.f);
}

__device__ __forceinline__ void red_add_v4(float* addr, float4 v) {
    asm volatile("red.global.v4.f32.add [%0], {%1, %2, %3, %4};"
                 :: "l"(addr), "f"(v.x), "f"(v.y), "f"(v.z), "f"(v.w)
                 : "memory");
}

// Scatter relation k; every thread also zeroes its strided share of block k+1.
__global__ void scatter_zero_kernel(const float4* __restrict__ feat,
                                    const int* __restrict__ s_idx,
                                    const int* __restrict__ d_idx,
                                    float* __restrict__ out,
                                    int n_edges, int nh,
                                    float4* __restrict__ zptr,  // may be null
                                    long long zn4) {
    long long gid = blockIdx.x * (long long)blockDim.x + threadIdx.x;
    long long T = (long long)gridDim.x * blockDim.x;

    // ---- zero share of next block (fire-and-forget stores) ----
    if (zptr) {
        for (long long z = gid; z < zn4; z += T)
            zptr[z] = make_float4(0.f, 0.f, 0.f, 0.f);
    }

    // ---- scatter ----
    int pair = (int)(gid >> 3);
    if (pair >= nh) return;
    int sub = (int)(gid & 7);

    int e0 = pair;
    int e1 = pair + nh;
    bool has1 = (e1 < n_edges);

    int s0 = __ldcs(s_idx + e0);
    int d0 = __ldcs(d_idx + e0);
    int s1 = has1 ? __ldcs(s_idx + e1) : 0;
    int d1 = has1 ? __ldcs(d_idx + e1) : 0;

    float4 v0 = __ldg(feat + (long long)s0 * 8 + sub);
    float4 v1 = has1 ? __ldg(feat + (long long)s1 * 8 + sub)
                     : make_float4(0.f, 0.f, 0.f, 0.f);

    red_add_v4(out + (long long)d0 * FEAT_D + sub * 4, v0);
    if (has1) red_add_v4(out + (long long)d1 * FEAT_D + sub * 4, v1);
}

extern "C" void kernel_launch(void* const* d_in, const int* in_sizes, int n_in,
                              void* d_out, int out_size) {
    const float* u2 = (const float*)d_in[0];
    const float* u3 = (const float*)d_in[1];

    const int* S[7] = {(const int*)d_in[2], (const int*)d_in[4],
                       (const int*)d_in[6], (const int*)d_in[8],
                       (const int*)d_in[10], (const int*)d_in[12],
                       (const int*)d_in[14]};
    const int* D[7] = {(const int*)d_in[3], (const int*)d_in[5],
                       (const int*)d_in[7], (const int*)d_in[9],
                       (const int*)d_in[11], (const int*)d_in[13],
                       (const int*)d_in[15]};

    const int N3 = in_sizes[2];
    const int N4 = in_sizes[6];

    int rows[7];
    const float* feat[7];
    for (int r = 0; r < 7; r++) {
        rows[r] = (r < 2) ? N3 : N4;
        feat[r] = (r < 5) ? u2 : u3;
    }

    float* out = (float*)d_out;
    float* blk[7];
    {
        float* o = out;
        for (int r = 0; r < 7; r++) {
            blk[r] = o;
            o += (long long)rows[r] * FEAT_D;
        }
    }

    // standalone zero of block 0
    {
        long long n4 = (long long)rows[0] * 8;
        zero_f4_kernel<<<(int)((n4 + 255) / 256), 256>>>((float4*)blk[0], n4);
    }

    // scatter r with interleaved zero of block r+1
    for (int r = 0; r < 7; r++) {
        int n_edges = rows[r];
        int nh = (n_edges + 1) / 2;
        long long scat_threads = (long long)nh * 8;
        long long zn4 = (r + 1 < 7) ? (long long)rows[r + 1] * 8 : 0;
        float4* zptr = (r + 1 < 7) ? (float4*)blk[r + 1] : nullptr;

        int grid = (int)((scat_threads + 255) / 256);
        scatter_zero_kernel<<<grid, 256>>>((const float4*)feat[r], S[r], D[r],
                                           blk[r], n_edges, nh, zptr, zn4);
    }
}